// round 1
// baseline (speedup 1.0000x reference)
#include <cuda_runtime.h>

#define NBOX   4096
#define NBATCH 16
#define MAXP   300
#define BT     1024
#define IOU_T  0.7f
#define SC_T   0.5f

struct Smem {
    unsigned long long sk[NBOX];   // sort keys: (~orderable(score))<<32 | idx
    float sx1[NBOX], sy1[NBOX], sx2[NBOX], sy2[NBOX];
    float sarea[NBOX];
    int   sidx[NBOX];
    unsigned char sup[NBOX];
    int   kept[MAXP];
    int   nk;
};

__global__ __launch_bounds__(BT, 1)
void nms_kernel(const float4* __restrict__ props,   // [B,N,4]
                const float2* __restrict__ cls,     // [B,N,2]
                float* __restrict__ outb,           // [B,300,4]
                float* __restrict__ outs)           // [B,300]
{
    extern __shared__ unsigned char smem_raw[];
    Smem& s = *reinterpret_cast<Smem*>(smem_raw);

    const int b   = blockIdx.x;
    const int tid = threadIdx.x;
    const float4* P = props + (size_t)b * NBOX;
    const float2* C = cls   + (size_t)b * NBOX;

    // ---- build sort keys: descending score, ascending index, invalid last ----
    for (int t = tid; t < NBOX; t += BT) {
        float sc = C[t].y;
        unsigned u;
        if (sc > SC_T) {
            // sc > 0 -> orderable ascending map is (bits | signbit); invert for descending
            u = ~(__float_as_uint(sc) | 0x80000000u);
        } else {
            u = 0xFF800000u;  // sentinel: sorts after every valid key
        }
        s.sk[t] = ((unsigned long long)u << 32) | (unsigned)t;
    }
    __syncthreads();

    // ---- bitonic sort (ascending 64-bit keys) ----
    for (int k = 2; k <= NBOX; k <<= 1) {
        for (int j = k >> 1; j > 0; j >>= 1) {
            for (int t = tid; t < NBOX; t += BT) {
                int ixj = t ^ j;
                if (ixj > t) {
                    unsigned long long a = s.sk[t], c = s.sk[ixj];
                    bool up = ((t & k) == 0);
                    if ((a > c) == up) { s.sk[t] = c; s.sk[ixj] = a; }
                }
            }
            __syncthreads();
        }
    }

    // ---- gather boxes in sorted order, init suppression ----
    for (int t = tid; t < NBOX; t += BT) {
        unsigned long long key = s.sk[t];
        int oi = (int)(key & 0xffffffffu);
        s.sidx[t] = oi;
        float4 p = P[oi];
        s.sx1[t] = p.x; s.sy1[t] = p.y; s.sx2[t] = p.z; s.sy2[t] = p.w;
        s.sarea[t] = __fmul_rn(p.z - p.x, p.w - p.y);
        s.sup[t] = ((unsigned)(key >> 32) == 0xFF800000u) ? 1 : 0;
    }
    if (tid == 0) s.nk = 0;
    __syncthreads();

    // ---- greedy NMS over sorted order, early exit at MAXP kept ----
    for (int i = 0; i < NBOX; ++i) {
        if (s.nk >= MAXP) break;        // consistent: nk only changes under barriers
        if (s.sup[i]) continue;         // consistent: sup[i] finalized by earlier barriers
        if (tid == 0) s.kept[s.nk] = i;
        float x1i = s.sx1[i], y1i = s.sy1[i];
        float x2i = s.sx2[i], y2i = s.sy2[i];
        float ai  = s.sarea[i];
        for (int j = i + 1 + tid; j < NBOX; j += BT) {
            if (s.sup[j]) continue;
            float xx1 = fmaxf(x1i, s.sx1[j]);
            float yy1 = fmaxf(y1i, s.sy1[j]);
            float xx2 = fminf(x2i, s.sx2[j]);
            float yy2 = fminf(y2i, s.sy2[j]);
            float w = fmaxf(__fadd_rn(xx2, -xx1), 0.0f);
            float h = fmaxf(__fadd_rn(yy2, -yy1), 0.0f);
            float inter = __fmul_rn(w, h);
            float denom = __fadd_rn(__fadd_rn(ai, s.sarea[j]), -inter);
            if (__fdiv_rn(inter, denom) >= IOU_T) s.sup[j] = 1;
        }
        __syncthreads();
        if (tid == 0) s.nk++;
        __syncthreads();
    }
    __syncthreads();

    // ---- emit first min(nk,300) kept (score order), pad with last kept ----
    int nk  = s.nk;
    int pad = (nk > 0) ? s.kept[nk - 1] : (NBOX - 1);   // nk==0: order[N-1], per reference clip
    for (int t = tid; t < MAXP; t += BT) {
        int pos = (t < nk) ? s.kept[t] : pad;
        int oi  = s.sidx[pos];
        reinterpret_cast<float4*>(outb)[b * MAXP + t] = P[oi];
        outs[b * MAXP + t] = C[oi].y;
    }
}

extern "C" void kernel_launch(void* const* d_in, const int* in_sizes, int n_in,
                              void* d_out, int out_size)
{
    const float4* props = (const float4*)d_in[0];
    const float2* cls   = (const float2*)d_in[1];
    float* outb = (float*)d_out;                          // [16,300,4]
    float* outs = (float*)d_out + NBATCH * MAXP * 4;      // [16,300]

    cudaFuncSetAttribute(nms_kernel,
                         cudaFuncAttributeMaxDynamicSharedMemorySize,
                         (int)sizeof(Smem));
    nms_kernel<<<NBATCH, BT, sizeof(Smem)>>>(props, cls, outb, outs);
}